// round 3
// baseline (speedup 1.0000x reference)
#include <cuda_runtime.h>
#include <cstdint>

// ---------------- problem constants ----------------
#define U_DIM     256
#define IN_DIM    64
#define T_STEPS   128
#define B_TOT     256
#define UNFOLDS   6
#define EPSV      1e-8f

// ---------------- decomposition ----------------
#define CL        8       // CTAs per cluster (post-dimension split)
#define POSTS     32      // posts per CTA   (256 / 8)
#define G_BATCH   16      // batches per cluster
#define NWARP     4
#define NTHREADS  128
#define NGROUPS   (B_TOT / G_BATCH)   // 16 clusters
#define NCTAS     (NGROUPS * CL)      // 128 CTAs

// ---------------- shared memory layout (bytes) ----------------
#define OFF_RPAR  0
#define SZ_RPAR   (U_DIM * POSTS * 16)          // float4[256][32] = 128 KB
#define OFF_SPAR  (OFF_RPAR + SZ_RPAR)
#define SZ_SPAR   (IN_DIM * POSTS * 16)         // float4[64][32]  = 32 KB
#define OFF_V     (OFF_SPAR + SZ_SPAR)
#define SZ_V      (2 * G_BATCH * U_DIM * 4)     // double-buffered v = 32 KB
#define OFF_PART  (OFF_V + SZ_V)
#define SZ_PART   (NWARP * G_BATCH * POSTS * 8) // float2 partials = 16 KB
#define OFF_SSUM  (OFF_PART + SZ_PART)
#define SZ_SSUM   (G_BATCH * POSTS * 8)         // sensory sums = 4 KB
#define OFF_X     (OFF_SSUM + SZ_SSUM)
#define SZ_X      (G_BATCH * IN_DIM * 4)        // staged x = 4 KB
#define OFF_MISC  (OFF_X + SZ_X)
#define SZ_MISC   ((G_BATCH + 3 * POSTS) * 4)
#define SMEM_TOTAL (OFF_MISC + SZ_MISC)         // ~221.6 KB

static_assert(SMEM_TOTAL < 232448, "smem over limit");

// ---------------- cluster helpers ----------------
__device__ __forceinline__ uint32_t smem_u32(const void* p) {
    return (uint32_t)__cvta_generic_to_shared(p);
}
__device__ __forceinline__ uint32_t mapa_rank(uint32_t laddr, uint32_t rank) {
    uint32_t r;
    asm("mapa.shared::cluster.u32 %0, %1, %2;" : "=r"(r) : "r"(laddr), "r"(rank));
    return r;
}
__device__ __forceinline__ void st_cluster_f32(uint32_t addr, float v) {
    asm volatile("st.shared::cluster.f32 [%0], %1;" :: "r"(addr), "f"(v) : "memory");
}
__device__ __forceinline__ void cluster_sync_all() {
    asm volatile("barrier.cluster.arrive.aligned;" ::: "memory");
    asm volatile("barrier.cluster.wait.aligned;"   ::: "memory");
}
__device__ __forceinline__ float ex2_approx(float x) {
    float r; asm("ex2.approx.f32 %0, %1;" : "=f"(r) : "f"(x)); return r;
}
__device__ __forceinline__ float rcp_approx(float x) {
    float r; asm("rcp.approx.f32 %0, %1;" : "=f"(r) : "f"(x)); return r;
}

// ---------------- kernel ----------------
__global__ void __launch_bounds__(NTHREADS, 1) ltc_kernel(
    const float* __restrict__ x,     const float* __restrict__ ts,
    const float* __restrict__ smu,   const float* __restrict__ ssig,
    const float* __restrict__ sw,    const float* __restrict__ serev,
    const float* __restrict__ rmu,   const float* __restrict__ rsig,
    const float* __restrict__ rw,    const float* __restrict__ rerev,
    const float* __restrict__ gleak, const float* __restrict__ vleak,
    const float* __restrict__ cm,
    const float* __restrict__ iw,    const float* __restrict__ ib,
    const float* __restrict__ ow,    const float* __restrict__ ob,
    const float* __restrict__ hw,    const float* __restrict__ hb,
    float* __restrict__ out)
{
    extern __shared__ char smem[];
    float4* RP   = (float4*)(smem + OFF_RPAR);  // [pre][lane] a,b,w,ws
    float4* SP   = (float4*)(smem + OFF_SPAR);
    float*  V    = (float*) (smem + OFF_V);     // [2][G][256]
    float2* PT   = (float2*)(smem + OFF_PART);  // [warp][g][lane] num,den
    float2* SS   = (float2*)(smem + OFF_SSUM);  // [g][lane]
    float*  XS   = (float*) (smem + OFF_X);     // [g][64]
    float*  MISC = (float*) (smem + OFF_MISC);
    float*  CMRT = MISC;                 // [16]  6/elapsed per batch
    float*  GL   = MISC + G_BATCH;       // [32]  gleak
    float*  GLVL = GL + POSTS;           // [32]  gleak*vleak
    float*  CMV  = GLVL + POSTS;         // [32]  cm

    const int tid  = threadIdx.x;
    const int warp = tid >> 5, lane = tid & 31;
    const int rank = blockIdx.x & (CL - 1);
    const int grp  = blockIdx.x >> 3;
    const int b0   = grp * G_BATCH;
    const int u0   = rank * POSTS;

    const float L2E = 1.4426950408889634f;

    // ---- one-time: transform params into SMEM (per-CTA post slice) ----
    for (int pre = warp; pre < U_DIM; pre += NWARP) {
        int gi = pre * U_DIM + u0 + lane;
        float sg = rsig[gi], m = rmu[gi], wv = rw[gi], er = rerev[gi];
        RP[pre * POSTS + lane] = make_float4(-L2E * sg, L2E * sg * m, wv, wv * er);
    }
    for (int pre = warp; pre < IN_DIM; pre += NWARP) {
        int gi = pre * U_DIM + u0 + lane;
        float sg = ssig[gi], m = smu[gi], wv = sw[gi], er = serev[gi];
        float a  = -L2E * sg;
        float bq = L2E * sg * m;
        // fold affine input map: z = a*(x*iw+ib)+bq = (a*iw)*x + (a*ib+bq)
        SP[pre * POSTS + lane] = make_float4(a * iw[pre], fmaf(a, ib[pre], bq), wv, wv * er);
    }
    if (tid < POSTS) {
        int u = u0 + tid;
        float g = gleak[u];
        GL[tid]   = g;
        GLVL[tid] = g * vleak[u];
        CMV[tid]  = cm[u];
    }
    for (int i = tid; i < 2 * G_BATCH * U_DIM; i += NTHREADS) V[i] = 0.f;

    cluster_sync_all();   // params + v0 visible cluster-wide before first use

    int cur = 0;
    for (int t = 0; t < T_STEPS; ++t) {
        // ---- stage x and per-batch time constants ----
        for (int k = tid; k < G_BATCH * IN_DIM; k += NTHREADS) {
            int g = k >> 6, i = k & 63;
            XS[k] = x[((size_t)(b0 + g) * T_STEPS + t) * IN_DIM + i];
        }
        if (tid < G_BATCH) {
            float el = ts[(size_t)(b0 + tid) * T_STEPS + t];
            CMRT[tid] = 6.0f / el;
        }
        __syncthreads();

        // ---- sensory partials (once per step) ----
        {
            float num[G_BATCH], den[G_BATCH];
            #pragma unroll
            for (int g = 0; g < G_BATCH; ++g) { num[g] = 0.f; den[g] = 0.f; }
            #pragma unroll 2
            for (int p = 0; p < IN_DIM / NWARP; ++p) {
                int pre = warp * (IN_DIM / NWARP) + p;
                float4 q = SP[pre * POSTS + lane];
                #pragma unroll
                for (int g = 0; g < G_BATCH; ++g) {
                    float z = fmaf(q.x, XS[g * IN_DIM + pre], q.y);
                    float r = rcp_approx(1.0f + ex2_approx(z));
                    den[g] = fmaf(q.z, r, den[g]);
                    num[g] = fmaf(q.w, r, num[g]);
                }
            }
            #pragma unroll
            for (int g = 0; g < G_BATCH; ++g)
                PT[(warp * G_BATCH + g) * POSTS + lane] = make_float2(num[g], den[g]);
        }
        __syncthreads();
        for (int k = tid; k < G_BATCH * POSTS; k += NTHREADS) {
            float n = 0.f, d = 0.f;
            #pragma unroll
            for (int w2 = 0; w2 < NWARP; ++w2) {
                float2 p = PT[w2 * G_BATCH * POSTS + k];
                n += p.x; d += p.y;
            }
            SS[k] = make_float2(n, d);
        }
        __syncthreads();

        // ---- 6 semi-implicit Euler unfolds ----
        for (int u = 0; u < UNFOLDS; ++u) {
            const float* vc = V + cur * (G_BATCH * U_DIM);
            float num[G_BATCH], den[G_BATCH];
            #pragma unroll
            for (int g = 0; g < G_BATCH; ++g) { num[g] = 0.f; den[g] = 0.f; }
            #pragma unroll 2
            for (int p = 0; p < U_DIM / NWARP; ++p) {
                int pre = warp * (U_DIM / NWARP) + p;
                float4 q = RP[pre * POSTS + lane];
                #pragma unroll
                for (int g = 0; g < G_BATCH; ++g) {
                    float z = fmaf(q.x, vc[g * U_DIM + pre], q.y);
                    float r = rcp_approx(1.0f + ex2_approx(z));
                    den[g] = fmaf(q.z, r, den[g]);
                    num[g] = fmaf(q.w, r, num[g]);
                }
            }
            #pragma unroll
            for (int g = 0; g < G_BATCH; ++g)
                PT[(warp * G_BATCH + g) * POSTS + lane] = make_float2(num[g], den[g]);
            __syncthreads();

            // reduce, v-update, scatter new v to every CTA in the cluster
            int nxt = cur ^ 1;
            for (int k = tid; k < G_BATCH * POSTS; k += NTHREADS) {
                int g = k >> 5, l = k & 31;
                float2 s = SS[k];
                float n = s.x, d = s.y;
                #pragma unroll
                for (int w2 = 0; w2 < NWARP; ++w2) {
                    float2 p = PT[w2 * G_BATCH * POSTS + k];
                    n += p.x; d += p.y;
                }
                float cmt   = CMRT[g] * CMV[l];
                float vold  = vc[g * U_DIM + u0 + l];
                float numer = fmaf(cmt, vold, GLVL[l]) + n;
                float denom = cmt + GL[l] + d + EPSV;
                float vnew  = __fdividef(numer, denom);
                uint32_t la = smem_u32(&V[(nxt * G_BATCH + g) * U_DIM + u0 + l]);
                #pragma unroll
                for (int r2 = 0; r2 < CL; ++r2)
                    st_cluster_f32(mapa_rank(la, (uint32_t)r2), vnew);
            }
            cluster_sync_all();
            cur = nxt;
        }
    }

    // ---- output head: rank 0 of each cluster holds the full final v ----
    if (rank == 0) {
        const float* vf = V + cur * (G_BATCH * U_DIM);
        for (int g = warp * 4; g < warp * 4 + 4; ++g) {
            float acc = 0.f;
            #pragma unroll
            for (int u = lane; u < U_DIM; u += 32) {
                float h = fmaf(vf[g * U_DIM + u], ow[u], ob[u]);
                acc = fmaf(h, hw[u], acc);
            }
            #pragma unroll
            for (int o = 16; o; o >>= 1) acc += __shfl_xor_sync(0xffffffffu, acc, o);
            if (lane == 0) out[b0 + g] = acc + hb[0];
        }
    }
}

// ---------------- launch ----------------
extern "C" void kernel_launch(void* const* d_in, const int* in_sizes, int n_in,
                              void* d_out, int out_size) {
    (void)in_sizes; (void)n_in; (void)out_size;
    cudaFuncSetAttribute(ltc_kernel, cudaFuncAttributeMaxDynamicSharedMemorySize, SMEM_TOTAL);

    cudaLaunchConfig_t cfg = {};
    cfg.gridDim  = dim3(NCTAS, 1, 1);
    cfg.blockDim = dim3(NTHREADS, 1, 1);
    cfg.dynamicSmemBytes = SMEM_TOTAL;
    cfg.stream = 0;
    cudaLaunchAttribute attrs[1];
    attrs[0].id = cudaLaunchAttributeClusterDimension;
    attrs[0].val.clusterDim.x = CL;
    attrs[0].val.clusterDim.y = 1;
    attrs[0].val.clusterDim.z = 1;
    cfg.attrs = attrs;
    cfg.numAttrs = 1;

    cudaLaunchKernelEx(&cfg, ltc_kernel,
        (const float*)d_in[0],  (const float*)d_in[1],
        (const float*)d_in[2],  (const float*)d_in[3],
        (const float*)d_in[4],  (const float*)d_in[5],
        (const float*)d_in[6],  (const float*)d_in[7],
        (const float*)d_in[8],  (const float*)d_in[9],
        (const float*)d_in[10], (const float*)d_in[11],
        (const float*)d_in[12], (const float*)d_in[13],
        (const float*)d_in[14], (const float*)d_in[15],
        (const float*)d_in[16], (const float*)d_in[17],
        (const float*)d_in[18],
        (float*)d_out);
}

// round 4
// speedup vs baseline: 1.9288x; 1.9288x over previous
#include <cuda_runtime.h>
#include <cstdint>

// ---------------- problem constants ----------------
#define U_DIM     256
#define IN_DIM    64
#define T_STEPS   128
#define B_TOT     256
#define UNFOLDS   6
#define EPSV      1e-8f

// ---------------- decomposition ----------------
#define CL        8       // CTAs per cluster (post-dimension split)
#define POSTS     32      // posts per CTA   (256 / 8)
#define G_BATCH   16      // batches per cluster
#define G_HALF    8       // batches per warp (g split in 2)
#define PCHUNK    4       // pre chunks
#define NWARP     8
#define NTHREADS  256
#define NGROUPS   (B_TOT / G_BATCH)   // 16 clusters
#define NCTAS     (NGROUPS * CL)      // 128 CTAs

// ---------------- shared memory layout (bytes) ----------------
#define OFF_RPAR  0
#define SZ_RPAR   (U_DIM * POSTS * 16)          // float4[256][32] = 128 KB
#define OFF_SPAR  (OFF_RPAR + SZ_RPAR)
#define SZ_SPAR   (IN_DIM * POSTS * 16)         // float4[64][32]  = 32 KB
#define OFF_V     (OFF_SPAR + SZ_SPAR)
#define SZ_V      (2 * G_BATCH * U_DIM * 4)     // double-buffered v = 32 KB
#define OFF_PART  (OFF_V + SZ_V)
#define SZ_PART   (PCHUNK * G_BATCH * POSTS * 8) // float2 partials = 16 KB
#define OFF_SSUM  (OFF_PART + SZ_PART)
#define SZ_SSUM   (G_BATCH * POSTS * 8)         // sensory tanh sums = 4 KB
#define OFF_X     (OFF_SSUM + SZ_SSUM)
#define SZ_X      (G_BATCH * IN_DIM * 4)        // staged x = 4 KB
#define OFF_MISC  (OFF_X + SZ_X)
#define SZ_MISC   ((G_BATCH + 3 * POSTS) * 4)
#define SMEM_TOTAL (OFF_MISC + SZ_MISC)         // ~221.6 KB

static_assert(SMEM_TOTAL < 232448, "smem over limit");

// ---------------- helpers ----------------
__device__ __forceinline__ uint32_t smem_u32(const void* p) {
    return (uint32_t)__cvta_generic_to_shared(p);
}
__device__ __forceinline__ uint32_t mapa_rank(uint32_t laddr, uint32_t rank) {
    uint32_t r;
    asm("mapa.shared::cluster.u32 %0, %1, %2;" : "=r"(r) : "r"(laddr), "r"(rank));
    return r;
}
__device__ __forceinline__ void st_cluster_f32(uint32_t addr, float v) {
    asm volatile("st.shared::cluster.f32 [%0], %1;" :: "r"(addr), "f"(v) : "memory");
}
__device__ __forceinline__ void cluster_sync_all() {
    asm volatile("barrier.cluster.arrive.aligned;" ::: "memory");
    asm volatile("barrier.cluster.wait.aligned;"   ::: "memory");
}
__device__ __forceinline__ float tanh_fast(float x) {
    float r; asm("tanh.approx.f32 %0, %1;" : "=f"(r) : "f"(x)); return r;
}

// ---------------- kernel ----------------
__global__ void __launch_bounds__(NTHREADS, 1) ltc_kernel(
    const float* __restrict__ x,     const float* __restrict__ ts,
    const float* __restrict__ smu,   const float* __restrict__ ssig,
    const float* __restrict__ sw,    const float* __restrict__ serev,
    const float* __restrict__ rmu,   const float* __restrict__ rsig,
    const float* __restrict__ rw,    const float* __restrict__ rerev,
    const float* __restrict__ gleak, const float* __restrict__ vleak,
    const float* __restrict__ cm,
    const float* __restrict__ iw,    const float* __restrict__ ib,
    const float* __restrict__ ow,    const float* __restrict__ ob,
    const float* __restrict__ hw,    const float* __restrict__ hb,
    float* __restrict__ out)
{
    extern __shared__ char smem[];
    float4* RP   = (float4*)(smem + OFF_RPAR);  // [pre][lane]  a,b,w/2,w*erev/2
    float4* SP   = (float4*)(smem + OFF_SPAR);
    float*  V    = (float*) (smem + OFF_V);     // [2][G][256]
    float2* PT   = (float2*)(smem + OFF_PART);  // [pc][g][lane] num_t,den_t
    float2* SS   = (float2*)(smem + OFF_SSUM);  // [g][lane] sensory tanh sums
    float*  XS   = (float*) (smem + OFF_X);     // [g][64]
    float*  MISC = (float*) (smem + OFF_MISC);
    float*  CMRT = MISC;                 // [16]  6/elapsed per batch
    float*  NB   = MISC + G_BATCH;       // [32]  numerator base (gleak*vleak + Σw*erev/2)
    float*  DB   = NB + POSTS;           // [32]  denominator base (gleak + eps + Σw/2)
    float*  CMV  = DB + POSTS;           // [32]  cm

    const int tid  = threadIdx.x;
    const int warp = tid >> 5, lane = tid & 31;
    const int pc   = warp >> 1;          // pre-chunk [0,4)
    const int gh   = warp & 1;           // g-half    [0,2)
    const int rank = blockIdx.x & (CL - 1);
    const int grp  = blockIdx.x >> 3;
    const int b0   = grp * G_BATCH;
    const int u0   = rank * POSTS;

    // ---- one-time: transform params into SMEM (per-CTA post slice) ----
    // sigmoid(sg*(v-mu)) = 0.5 + 0.5*tanh(0.5*sg*v - 0.5*sg*mu)
    for (int pre = warp; pre < U_DIM; pre += NWARP) {
        int gi = pre * U_DIM + u0 + lane;
        float sg = rsig[gi], m = rmu[gi], wv = rw[gi], er = rerev[gi];
        RP[pre * POSTS + lane] = make_float4(0.5f * sg, -0.5f * sg * m,
                                             0.5f * wv,  0.5f * wv * er);
    }
    for (int pre = warp; pre < IN_DIM; pre += NWARP) {
        int gi = pre * U_DIM + u0 + lane;
        float sg = ssig[gi], m = smu[gi], wv = sw[gi], er = serev[gi];
        // fold input affine: arg = 0.5*sg*((x*iw+ib)-mu)
        SP[pre * POSTS + lane] = make_float4(0.5f * sg * iw[pre],
                                             0.5f * sg * (ib[pre] - m),
                                             0.5f * wv, 0.5f * wv * er);
    }
    for (int i = tid; i < 2 * G_BATCH * U_DIM; i += NTHREADS) V[i] = 0.f;
    __syncthreads();
    if (tid < POSTS) {
        float w2s = 0.f, we2s = 0.f;
        for (int pre = 0; pre < U_DIM; ++pre) {
            float4 q = RP[pre * POSTS + tid]; w2s += q.z; we2s += q.w;
        }
        for (int pre = 0; pre < IN_DIM; ++pre) {
            float4 q = SP[pre * POSTS + tid]; w2s += q.z; we2s += q.w;
        }
        int u = u0 + tid;
        float gk = gleak[u];
        DB[tid]  = gk + EPSV + w2s;
        NB[tid]  = gk * vleak[u] + we2s;
        CMV[tid] = cm[u];
    }

    cluster_sync_all();   // params + v0 visible cluster-wide before first use

    int cur = 0;
    for (int t = 0; t < T_STEPS; ++t) {
        // ---- stage x and per-batch time constants ----
        for (int k = tid; k < G_BATCH * IN_DIM; k += NTHREADS) {
            int g = k >> 6, i = k & 63;
            XS[k] = x[((size_t)(b0 + g) * T_STEPS + t) * IN_DIM + i];
        }
        if (tid < G_BATCH) {
            float el = ts[(size_t)(b0 + tid) * T_STEPS + t];
            CMRT[tid] = 6.0f / el;
        }
        __syncthreads();

        // ---- sensory tanh partials (once per step) ----
        {
            float num[G_HALF], den[G_HALF];
            #pragma unroll
            for (int g = 0; g < G_HALF; ++g) { num[g] = 0.f; den[g] = 0.f; }
            const int pbase = pc * (IN_DIM / PCHUNK);   // 16 pres / warp
            #pragma unroll
            for (int pt = 0; pt < IN_DIM / PCHUNK / 4; ++pt) {
                int p0 = pbase + pt * 4;
                float4 q0 = SP[(p0 + 0) * POSTS + lane];
                float4 q1 = SP[(p0 + 1) * POSTS + lane];
                float4 q2 = SP[(p0 + 2) * POSTS + lane];
                float4 q3 = SP[(p0 + 3) * POSTS + lane];
                #pragma unroll
                for (int gg = 0; gg < G_HALF; ++gg) {
                    int g = gh * G_HALF + gg;
                    float4 xv = *(const float4*)&XS[g * IN_DIM + p0];
                    float t0 = tanh_fast(fmaf(q0.x, xv.x, q0.y));
                    float t1 = tanh_fast(fmaf(q1.x, xv.y, q1.y));
                    float t2 = tanh_fast(fmaf(q2.x, xv.z, q2.y));
                    float t3 = tanh_fast(fmaf(q3.x, xv.w, q3.y));
                    den[gg] = fmaf(q0.z, t0, den[gg]); num[gg] = fmaf(q0.w, t0, num[gg]);
                    den[gg] = fmaf(q1.z, t1, den[gg]); num[gg] = fmaf(q1.w, t1, num[gg]);
                    den[gg] = fmaf(q2.z, t2, den[gg]); num[gg] = fmaf(q2.w, t2, num[gg]);
                    den[gg] = fmaf(q3.z, t3, den[gg]); num[gg] = fmaf(q3.w, t3, num[gg]);
                }
            }
            #pragma unroll
            for (int gg = 0; gg < G_HALF; ++gg)
                PT[(pc * G_BATCH + gh * G_HALF + gg) * POSTS + lane] =
                    make_float2(num[gg], den[gg]);
        }
        __syncthreads();
        for (int k = tid; k < G_BATCH * POSTS; k += NTHREADS) {
            float n = 0.f, d = 0.f;
            #pragma unroll
            for (int c = 0; c < PCHUNK; ++c) {
                float2 p = PT[c * G_BATCH * POSTS + k];
                n += p.x; d += p.y;
            }
            SS[k] = make_float2(n, d);
        }
        __syncthreads();

        // ---- 6 semi-implicit Euler unfolds ----
        for (int u = 0; u < UNFOLDS; ++u) {
            const float* vc = V + cur * (G_BATCH * U_DIM);
            float num[G_HALF], den[G_HALF];
            #pragma unroll
            for (int g = 0; g < G_HALF; ++g) { num[g] = 0.f; den[g] = 0.f; }
            const int pbase = pc * (U_DIM / PCHUNK);    // 64 pres / warp
            #pragma unroll 4
            for (int pt = 0; pt < U_DIM / PCHUNK / 4; ++pt) {
                int p0 = pbase + pt * 4;
                float4 q0 = RP[(p0 + 0) * POSTS + lane];
                float4 q1 = RP[(p0 + 1) * POSTS + lane];
                float4 q2 = RP[(p0 + 2) * POSTS + lane];
                float4 q3 = RP[(p0 + 3) * POSTS + lane];
                #pragma unroll
                for (int gg = 0; gg < G_HALF; ++gg) {
                    int g = gh * G_HALF + gg;
                    float4 vv = *(const float4*)&vc[g * U_DIM + p0];
                    float t0 = tanh_fast(fmaf(q0.x, vv.x, q0.y));
                    float t1 = tanh_fast(fmaf(q1.x, vv.y, q1.y));
                    float t2 = tanh_fast(fmaf(q2.x, vv.z, q2.y));
                    float t3 = tanh_fast(fmaf(q3.x, vv.w, q3.y));
                    den[gg] = fmaf(q0.z, t0, den[gg]); num[gg] = fmaf(q0.w, t0, num[gg]);
                    den[gg] = fmaf(q1.z, t1, den[gg]); num[gg] = fmaf(q1.w, t1, num[gg]);
                    den[gg] = fmaf(q2.z, t2, den[gg]); num[gg] = fmaf(q2.w, t2, num[gg]);
                    den[gg] = fmaf(q3.z, t3, den[gg]); num[gg] = fmaf(q3.w, t3, num[gg]);
                }
            }
            #pragma unroll
            for (int gg = 0; gg < G_HALF; ++gg)
                PT[(pc * G_BATCH + gh * G_HALF + gg) * POSTS + lane] =
                    make_float2(num[gg], den[gg]);
            __syncthreads();

            // reduce, v-update, scatter new v to every CTA in the cluster
            int nxt = cur ^ 1;
            for (int k = tid; k < G_BATCH * POSTS; k += NTHREADS) {
                int g = k >> 5, l = k & 31;
                float2 s = SS[k];
                float n = s.x, d = s.y;
                #pragma unroll
                for (int c = 0; c < PCHUNK; ++c) {
                    float2 p = PT[c * G_BATCH * POSTS + k];
                    n += p.x; d += p.y;
                }
                float cmt   = CMRT[g] * CMV[l];
                float vold  = vc[g * U_DIM + u0 + l];
                float numer = fmaf(cmt, vold, NB[l]) + n;
                float denom = cmt + DB[l] + d;
                float vnew  = __fdividef(numer, denom);
                uint32_t la = smem_u32(&V[(nxt * G_BATCH + g) * U_DIM + u0 + l]);
                #pragma unroll
                for (int r2 = 0; r2 < CL; ++r2)
                    st_cluster_f32(mapa_rank(la, (uint32_t)r2), vnew);
            }
            cluster_sync_all();
            cur = nxt;
        }
    }

    // ---- output head: rank 0 of each cluster holds the full final v ----
    if (rank == 0) {
        const float* vf = V + cur * (G_BATCH * U_DIM);
        for (int g = warp * 2; g < warp * 2 + 2; ++g) {
            float acc = 0.f;
            #pragma unroll
            for (int u = lane; u < U_DIM; u += 32) {
                float h = fmaf(vf[g * U_DIM + u], ow[u], ob[u]);
                acc = fmaf(h, hw[u], acc);
            }
            #pragma unroll
            for (int o = 16; o; o >>= 1) acc += __shfl_xor_sync(0xffffffffu, acc, o);
            if (lane == 0) out[b0 + g] = acc + hb[0];
        }
    }
}

// ---------------- launch ----------------
extern "C" void kernel_launch(void* const* d_in, const int* in_sizes, int n_in,
                              void* d_out, int out_size) {
    (void)in_sizes; (void)n_in; (void)out_size;
    cudaFuncSetAttribute(ltc_kernel, cudaFuncAttributeMaxDynamicSharedMemorySize, SMEM_TOTAL);

    cudaLaunchConfig_t cfg = {};
    cfg.gridDim  = dim3(NCTAS, 1, 1);
    cfg.blockDim = dim3(NTHREADS, 1, 1);
    cfg.dynamicSmemBytes = SMEM_TOTAL;
    cfg.stream = 0;
    cudaLaunchAttribute attrs[1];
    attrs[0].id = cudaLaunchAttributeClusterDimension;
    attrs[0].val.clusterDim.x = CL;
    attrs[0].val.clusterDim.y = 1;
    attrs[0].val.clusterDim.z = 1;
    cfg.attrs = attrs;
    cfg.numAttrs = 1;

    cudaLaunchKernelEx(&cfg, ltc_kernel,
        (const float*)d_in[0],  (const float*)d_in[1],
        (const float*)d_in[2],  (const float*)d_in[3],
        (const float*)d_in[4],  (const float*)d_in[5],
        (const float*)d_in[6],  (const float*)d_in[7],
        (const float*)d_in[8],  (const float*)d_in[9],
        (const float*)d_in[10], (const float*)d_in[11],
        (const float*)d_in[12], (const float*)d_in[13],
        (const float*)d_in[14], (const float*)d_in[15],
        (const float*)d_in[16], (const float*)d_in[17],
        (const float*)d_in[18],
        (float*)d_out);
}